// round 16
// baseline (speedup 1.0000x reference)
#include <cuda_runtime.h>
#include <cuda_fp16.h>

#define Bn 4
#define Cn 64
#define Hn 128
#define Wn 128
#define HWn (Hn*Wn)

typedef unsigned long long u64;

// packed f32x2 helpers (sm_103a): 2 fp32 MACs per instruction, RN rounding
__device__ __forceinline__ u64 pk2(float a, float b) {
    u64 r; asm("mov.b64 %0, {%1, %2};" : "=l"(r) : "f"(a), "f"(b)); return r;
}
__device__ __forceinline__ void fma2(u64& d, u64 a, u64 b) {
    asm("fma.rn.f32x2 %0, %1, %2, %0;" : "+l"(d) : "l"(a), "l"(b));
}
__device__ __forceinline__ float2 up2(u64 v) {
    float2 r; asm("mov.b64 {%0, %1}, %2;" : "=f"(r.x), "=f"(r.y) : "l"(v)); return r;
}

// ---------------- scratch ----------------
__device__ __align__(16) float g_xT[Bn*HWn*Cn];       // x  in [B,H,W,C]
__device__ __align__(16) float g_interT[Bn*HWn*Cn];   // inter in [B,H,W,C]
__device__ __align__(16) float g_sft[Bn*HWn*Cn];      // x + x*gamma + beta, pixel-major
__device__ __align__(16) float g_om[Bn*HWn*32];       // offsets+mask, pixel-major, pad 32
__device__ __align__(16) float g_woffT[1152*32];      // [r=cin*9+tap][o(pad32)]
__device__ __align__(16) float g_wdcnT[576*64];       // [r=c*9+k][o]
__device__ __align__(16) float g_wg1T[4096];          // [c][o]
__device__ __align__(16) float g_wg2T[4096];
__device__ __align__(16) float g_wb1T[4096];
__device__ __align__(16) float g_wb2T[4096];

// ---------------- weight prep ----------------
__global__ void prep_weights(const float* __restrict__ w_off,
                             const float* __restrict__ w_dcn,
                             const float* __restrict__ wg1, const float* __restrict__ wg2,
                             const float* __restrict__ wb1, const float* __restrict__ wb2) {
    int idx = blockIdx.x * blockDim.x + threadIdx.x;
    if (idx < 1152*32) {
        int r = idx >> 5, o = idx & 31;
        g_woffT[idx] = (o < 27) ? w_off[o*1152 + r] : 0.f;
    }
    if (idx < 576*64) {
        int r = idx >> 6, o = idx & 63;
        g_wdcnT[idx] = w_dcn[o*576 + r];
    }
    if (idx < 4096) {
        int c = idx >> 6, o = idx & 63;
        g_wg1T[idx] = wg1[o*64 + c];
        g_wg2T[idx] = wg2[o*64 + c];
        g_wb1T[idx] = wb1[o*64 + c];
        g_wb2T[idx] = wb2[o*64 + c];
    }
}

// ---------------- NCHW -> NHWC transpose (x + inter in one launch) ----------------
__global__ void transpose_k(const float* __restrict__ in_x, const float* __restrict__ in_i) {
    __shared__ float tile[32][33];
    int z = blockIdx.z;
    int b = z & 3;
    const float* in = (z & 4) ? in_i : in_x;
    float* out = (z & 4) ? g_interT : g_xT;
    int n0 = blockIdx.x * 32;
    int c0 = blockIdx.y * 32;
    int tx = threadIdx.x, ty = threadIdx.y;
    const float* src = in + (size_t)b * Cn * HWn;
    float* dst = out + (size_t)b * HWn * Cn;
#pragma unroll
    for (int i = 0; i < 32; i += 8)
        tile[ty + i][tx] = src[(size_t)(c0 + ty + i) * HWn + n0 + tx];
    __syncthreads();
#pragma unroll
    for (int i = 0; i < 32; i += 8)
        dst[(size_t)(n0 + ty + i) * Cn + c0 + tx] = tile[tx][ty + i];
}

// ---------------- offset conv (unchanged — near its floor) ----------------
__global__ __launch_bounds__(128) void offset_conv_k(
    const float* __restrict__ x, const float* __restrict__ inter,
    const float* __restrict__ b_off) {
    __shared__ __align__(16) float s_in[32 * 204];   // [ci][ry(3)][cx(68)] = 26112 B
    int b = blockIdx.z, h = blockIdx.y, w0 = blockIdx.x * 64;
    int tid = threadIdx.x;
    int og = tid & 7, quad = tid >> 3;
    int o0 = og * 4, p0 = quad * 4;
    u64 acc[4][2] = {{0,0},{0,0},{0,0},{0,0}};   // [px][out-pair]

    for (int half = 0; half < 2; ++half) {
        const float* src = half ? inter : x;
        for (int chunk = 0; chunk < 2; ++chunk) {
            int cbase = chunk * 32;
            __syncthreads();
            for (int idx = tid; idx < 32 * 204; idx += 128) {
                int ci = idx / 204; int rem = idx - ci * 204;
                int ry = rem / 68;  int cx = rem - ry * 68;
                int y = h - 1 + ry, xw = w0 - 1 + cx;
                float v = 0.f;
                if (cx < 66 && (unsigned)y < (unsigned)Hn && (unsigned)xw < (unsigned)Wn)
                    v = src[((size_t)(b * Cn + cbase + ci) * Hn + y) * Wn + xw];
                s_in[idx] = v;
            }
            __syncthreads();
            const float* wb = g_woffT + (half * 64 + cbase) * 288 + o0;
            for (int ci = 0; ci < 32; ++ci) {
                const float* srow = s_in + ci * 204 + p0;
                const float* wr = wb + ci * 288;
#pragma unroll
                for (int ry = 0; ry < 3; ++ry) {
                    float4 u0 = *(const float4*)(srow + ry * 68);
                    float2 u1 = *(const float2*)(srow + ry * 68 + 4);
                    u64 vp[6];
                    vp[0] = pk2(u0.x, u0.x); vp[1] = pk2(u0.y, u0.y);
                    vp[2] = pk2(u0.z, u0.z); vp[3] = pk2(u0.w, u0.w);
                    vp[4] = pk2(u1.x, u1.x); vp[5] = pk2(u1.y, u1.y);
#pragma unroll
                    for (int kx = 0; kx < 3; ++kx) {
                        ulonglong2 wp = *(const ulonglong2*)(wr + (ry * 3 + kx) * 32);
#pragma unroll
                        for (int px = 0; px < 4; ++px) {
                            fma2(acc[px][0], wp.x, vp[kx + px]);
                            fma2(acc[px][1], wp.y, vp[kx + px]);
                        }
                    }
                }
            }
        }
    }

    float bj[4];
#pragma unroll
    for (int j = 0; j < 4; ++j) bj[j] = (o0 + j < 27) ? b_off[o0 + j] : 0.f;

    size_t pixbase = ((size_t)b * Hn + h) * Wn + w0;
#pragma unroll
    for (int px = 0; px < 4; ++px) {
        float2 q0 = up2(acc[px][0]);
        float2 q1 = up2(acc[px][1]);
        float vals[4] = {q0.x, q0.y, q1.x, q1.y};
        float4 r;
        float* rv = (float*)&r;
#pragma unroll
        for (int j = 0; j < 4; ++j) {
            int o = o0 + j;
            float vv = vals[j] + bj[j];
            if (o >= 18 && o < 27) vv = 1.f / (1.f + expf(-vv));
            rv[j] = vv;
        }
        *(float4*)(g_om + (pixbase + p0 + px) * 32 + o0) = r;
    }
}

__device__ __forceinline__ float lrelu(float v) { return v >= 0.f ? v : 0.1f * v; }

// ---------------- SFT kernel: g_sft = x + x*gamma + beta  (pixel-major) ----------
// 128 thr / 32 px: og = tid&15 (16 x 4 out), t = tid>>4 (8 x 4 px).
// smem 25216 B -> 8 blocks/SM.
__global__ __launch_bounds__(128, 8) void sft_k() {
    __shared__ float s_iv[32 * 65];
    __shared__ float s_t1[32 * 66];
    __shared__ float s_t2[32 * 66];

    int b = blockIdx.z, h = blockIdx.y, w0 = blockIdx.x * 32;
    int tid = threadIdx.x;
    int og = tid & 15, t = tid >> 4, o0 = og * 4;
    int p0 = 4 * t;
    size_t pixbase = ((size_t)b * Hn + h) * Wn + w0;

    for (int idx = tid; idx < 32 * 64; idx += 128) {
        int pp = idx >> 6, c = idx & 63;
        s_iv[pp * 65 + c] = g_interT[(pixbase + pp) * 64 + c];
    }
    __syncthreads();

    // stage 1
    {
        u64 a1p[4][2] = {{0,0},{0,0},{0,0},{0,0}};
        u64 a2p[4][2] = {{0,0},{0,0},{0,0},{0,0}};
#pragma unroll 4
        for (int c = 0; c < 64; ++c) {
            ulonglong2 w1 = *(const ulonglong2*)(g_wg1T + c * 64 + o0);
            ulonglong2 w2 = *(const ulonglong2*)(g_wb1T + c * 64 + o0);
#pragma unroll
            for (int i = 0; i < 4; ++i) {
                float v = s_iv[(p0 + i) * 65 + c];
                u64 vp = pk2(v, v);
                fma2(a1p[i][0], w1.x, vp); fma2(a1p[i][1], w1.y, vp);
                fma2(a2p[i][0], w2.x, vp); fma2(a2p[i][1], w2.y, vp);
            }
        }
#pragma unroll
        for (int i = 0; i < 4; ++i) {
            float2 q0 = up2(a1p[i][0]), q1 = up2(a1p[i][1]);
            float2 r0 = up2(a2p[i][0]), r1 = up2(a2p[i][1]);
            float* t1p = s_t1 + (p0 + i) * 66 + o0;
            float* t2p = s_t2 + (p0 + i) * 66 + o0;
            t1p[0] = lrelu(q0.x); t1p[1] = lrelu(q0.y); t1p[2] = lrelu(q1.x); t1p[3] = lrelu(q1.y);
            t2p[0] = lrelu(r0.x); t2p[1] = lrelu(r0.y); t2p[2] = lrelu(r1.x); t2p[3] = lrelu(r1.y);
        }
    }
    __syncthreads();

    // stage 2
    u64 gmp[4][2] = {{0,0},{0,0},{0,0},{0,0}};
    u64 btp[4][2] = {{0,0},{0,0},{0,0},{0,0}};
#pragma unroll 4
    for (int c = 0; c < 64; ++c) {
        ulonglong2 w1 = *(const ulonglong2*)(g_wg2T + c * 64 + o0);
        ulonglong2 w2 = *(const ulonglong2*)(g_wb2T + c * 64 + o0);
#pragma unroll
        for (int i = 0; i < 4; ++i) {
            float u = s_t1[(p0 + i) * 66 + c];
            float v = s_t2[(p0 + i) * 66 + c];
            u64 upk = pk2(u, u), vpk = pk2(v, v);
            fma2(gmp[i][0], w1.x, upk); fma2(gmp[i][1], w1.y, upk);
            fma2(btp[i][0], w2.x, vpk); fma2(btp[i][1], w2.y, vpk);
        }
    }

    // epilogue: g_sft = x + x*gamma + beta  (pixel-major float4 stores)
#pragma unroll
    for (int i = 0; i < 4; ++i) {
        float2 g0 = up2(gmp[i][0]), g1 = up2(gmp[i][1]);
        float2 b0 = up2(btp[i][0]), b1 = up2(btp[i][1]);
        float4 xq = *(const float4*)(g_xT + (pixbase + p0 + i) * 64 + o0);
        float4 r;
        r.x = xq.x + xq.x * g0.x + b0.x;
        r.y = xq.y + xq.y * g0.y + b0.y;
        r.z = xq.z + xq.z * g1.x + b1.x;
        r.w = xq.w + xq.w * g1.y + b1.y;
        *(float4*)(g_sft + (pixbase + p0 + i) * 64 + o0) = r;
    }
}

// ---------------- DCN kernel: sampling + DCN + (out = sft + dcn) ----------------
// 128 thr / 32 px, channel-half ping-pong: sample c in [32hf,32hf+32) -> DCN 288 rows.
// smem: s_samph [288][36] fp16 (20736 B) + s_om [32][27] (3456 B) = 24192 B
// -> 7 blocks/SM (28 warps).
__global__ __launch_bounds__(128, 7) void dcn_k(float* __restrict__ out) {
    __shared__ __align__(16) __half s_samph[288 * 36];
    __shared__ float s_om[32 * 27];

    int b = blockIdx.z, h = blockIdx.y, w0 = blockIdx.x * 32;
    int tid = threadIdx.x;
    int og = tid & 15, t = tid >> 4, o0 = og * 4;
    int p0 = 4 * t;
    int wi = tid >> 5, lane = tid & 31;
    size_t pixbase = ((size_t)b * Hn + h) * Wn + w0;

    for (int idx = tid; idx < 32 * 27; idx += 128) {
        int pp = idx / 27, c = idx - pp * 27;
        s_om[idx] = g_om[(pixbase + pp) * 32 + c];
    }

    u64 dp[4][2] = {{0,0},{0,0},{0,0},{0,0}};   // [px][out-pair], persists across halves

    for (int hf = 0; hf < 2; ++hf) {
        __syncthreads();   // hf=0: s_om ready; hf=1: prior DCN reads done
        // sampling: c = lane + 32*hf; write r_local = (c-32hf)*9+k
        for (int task = wi; task < 288; task += 4) {
            int pp = task / 9, k = task - pp * 9;
            float dy = s_om[pp * 27 + k];
            float dx = s_om[pp * 27 + 9 + k];
            float m  = s_om[pp * 27 + 18 + k];
            int ky = k / 3, kx = k - ky * 3;
            float py = (float)(h + ky - 1) + dy;
            float px = (float)(w0 + pp + kx - 1) + dx;
            float fy = floorf(py), fx = floorf(px);
            float wy = py - fy, wx = px - fx;
            int y0 = (int)fy, x0 = (int)fx;
            bool vy0 = (unsigned)y0 < (unsigned)Hn;
            bool vy1 = (unsigned)(y0 + 1) < (unsigned)Hn;
            bool vx0 = (unsigned)x0 < (unsigned)Wn;
            bool vx1 = (unsigned)(x0 + 1) < (unsigned)Wn;
            float w00 = (1.f - wy) * (1.f - wx) * m;
            float w01 = (1.f - wy) * wx * m;
            float w10 = wy * (1.f - wx) * m;
            float w11 = wy * wx * m;
            const float* xb = g_xT + (size_t)b * HWn * Cn
                              + ((long long)y0 * Wn + x0) * Cn + hf * 32;
            int c = lane;
            float v00 = (vy0 && vx0) ? xb[c] : 0.f;
            float v01 = (vy0 && vx1) ? xb[c + Cn] : 0.f;
            float v10 = (vy1 && vx0) ? xb[c + Wn * Cn] : 0.f;
            float v11 = (vy1 && vx1) ? xb[c + Wn * Cn + Cn] : 0.f;
            float val = v00 * w00 + v01 * w01 + v10 * w10 + v11 * w11;
            s_samph[(c * 9 + k) * 36 + pp] = __float2half_rn(val);
        }
        __syncthreads();

        // DCN over this half's 288 rows
        const float* wbase = g_wdcnT + hf * 288 * 64 + o0;
#pragma unroll 4
        for (int r = 0; r < 288; ++r) {
            ulonglong2 w2v = *(const ulonglong2*)(wbase + r * 64);
            uint2 hv = *(const uint2*)(s_samph + r * 36 + p0);   // 8B aligned
            float2 sp01 = __half22float2(*reinterpret_cast<const __half2*>(&hv.x));
            float2 sp23 = __half22float2(*reinterpret_cast<const __half2*>(&hv.y));
            u64 s0 = pk2(sp01.x, sp01.x);
            u64 s1 = pk2(sp01.y, sp01.y);
            u64 s2 = pk2(sp23.x, sp23.x);
            u64 s3 = pk2(sp23.y, sp23.y);
            fma2(dp[0][0], w2v.x, s0); fma2(dp[0][1], w2v.y, s0);
            fma2(dp[1][0], w2v.x, s1); fma2(dp[1][1], w2v.y, s1);
            fma2(dp[2][0], w2v.x, s2); fma2(dp[2][1], w2v.y, s2);
            fma2(dp[3][0], w2v.x, s3); fma2(dp[3][1], w2v.y, s3);
        }
    }

    // epilogue: out = sft + dcn   (NCHW, float4 across 4 pixels)
    float dv[4][4], sv[4][4];
#pragma unroll
    for (int i = 0; i < 4; ++i) {
        float2 q0 = up2(dp[i][0]), q1 = up2(dp[i][1]);
        dv[i][0] = q0.x; dv[i][1] = q0.y; dv[i][2] = q1.x; dv[i][3] = q1.y;
        float4 sq = *(const float4*)(g_sft + (pixbase + p0 + i) * 64 + o0);
        sv[i][0] = sq.x; sv[i][1] = sq.y; sv[i][2] = sq.z; sv[i][3] = sq.w;
    }
#pragma unroll
    for (int j = 0; j < 4; ++j) {
        float4 rr;
        rr.x = sv[0][j] + dv[0][j];
        rr.y = sv[1][j] + dv[1][j];
        rr.z = sv[2][j] + dv[2][j];
        rr.w = sv[3][j] + dv[3][j];
        *(float4*)(out + ((size_t)(b * Cn + o0 + j) * Hn + h) * Wn + w0 + p0) = rr;
    }
}

// ---------------- launch ----------------
extern "C" void kernel_launch(void* const* d_in, const int* in_sizes, int n_in,
                              void* d_out, int out_size) {
    const float* x     = (const float*)d_in[0];
    const float* inter = (const float*)d_in[1];
    const float* w_off = (const float*)d_in[2];
    const float* b_off = (const float*)d_in[3];
    const float* w_dcn = (const float*)d_in[4];
    const float* wg1   = (const float*)d_in[5];
    const float* wg2   = (const float*)d_in[6];
    const float* wb1   = (const float*)d_in[7];
    const float* wb2   = (const float*)d_in[8];
    float* out = (float*)d_out;

    prep_weights<<<144, 256>>>(w_off, w_dcn, wg1, wg2, wb1, wb2);
    transpose_k<<<dim3(HWn / 32, Cn / 32, 2 * Bn), dim3(32, 8)>>>(x, inter);
    offset_conv_k<<<dim3(Wn / 64, Hn, Bn), 128>>>(x, inter, b_off);
    sft_k<<<dim3(Wn / 32, Hn, Bn), 128>>>();
    dcn_k<<<dim3(Wn / 32, Hn, Bn), 128>>>(out);
}